// round 1
// baseline (speedup 1.0000x reference)
#include <cuda_runtime.h>
#include <math.h>

// ---------------------------------------------------------------------------
// E3nnForce fused kernel.
//
// Key facts derived from the reference:
//  * Each of nt = 64*512 = 32768 triplets is an independent 9-node graph.
//  * Output depends only on nodes 3,4,5 (middle row). Dependency closure:
//      node 4 <- node 1 (edge (1,4)), nodes 3,5 <- node 4 (edges (4,3),(4,5)).
//    Nodes 0,2,6,7,8 and the other 5 edges are dead.
//  * v[node1] == 0 for all layers (no incoming edges, multiplicative update).
//  * Aggregation is trivial: each live node receives exactly one message.
//
// Mapping: 64 threads per triplet, 8 triplets per 512-thread block.
// Per layer: stage weights to smem -> edge-MLP hidden (12->64) -> radial
// weights (64->250, float4-vectorized) -> messages -> node GEMMs (50x50 x3).
// ---------------------------------------------------------------------------

#define CC 50
#define HH 64
#define TRIPS 8
#define NBLK 4096          // 32768 / 8
#define NTHR 512

// per-triplet smem layout (floats); all float4-accessed regions are 16B aligned
#define OF_HID  0          // hidden[64][4]  (j-major, lanes = 3 edges + pad)
#define OF_HC   256        // hC[50][4]      (h for nodes {1,4,3,5})
#define OF_VC   456        // vC[50][12]     ((v+v_agg) for nodes {4,3,5} x 3d)
#define OF_U    1056       // u[3][4]
#define OF_W    1068       // w[3][252]      (radial weights, fcut applied)
#define OF_S    1824       // s[4][50]       nodes {1,4,3,5}
#define OF_V    2024       // v[3][50][3]    nodes {4,3,5}
#define OF_EMB  2474       // emb[3][12]
#define OF_Y2   2510       // Y2[3][9]
#define OF_FCUT 2537       // fcut[3]
#define OF_OFF  2540       // off1 (x,y) of middle row
#define TSF     2560

// block-shared weight staging (floats)
#define WR2_OFF 0          // 64 x 252 (rows padded 250->252)
#define WR1_OFF 16128      // 12 x 64
#define BR1_OFF 16896      // 64
#define WS_OFF  16960      // 50 x 50
#define WG_OFF  19460      // 50 x 50
#define WV_OFF  21960      // 50 x 50
#define TST_OFF 24460
#define SMEM_FLOATS (TST_OFF + TRIPS * TSF)   // 44940
#define SMEM_BYTES  (SMEM_FLOATS * 4)          // 179760

__device__ __forceinline__ float sigm_f(float x) { return 1.0f / (1.0f + __expf(-x)); }
__device__ __forceinline__ float silu_f(float x) { return x / (1.0f + __expf(-x)); }

__global__ void __launch_bounds__(NTHR, 1)
e3nn_kernel(const float* __restrict__ y,
            const float* __restrict__ Wemb,
            const float* __restrict__ Wr1g,
            const float* __restrict__ br1g,
            const float* __restrict__ Wr2g,
            const float* __restrict__ Wsg,
            const float* __restrict__ Wvg,
            const float* __restrict__ Wgg,
            const float* __restrict__ Woutg,
            float* __restrict__ outp)
{
    extern __shared__ float sm[];
    const int tid  = threadIdx.x;
    const int trip = tid >> 6;
    const int k    = tid & 63;
    float* ts = sm + TST_OFF + trip * TSF;

    const int t = blockIdx.x * TRIPS + trip;   // global triplet id, < 32768
    const int b = t >> 9;                       // batch
    const int i = t & 511;                      // position (T = 512)

    // ---------------- geometry (once) ----------------
    if (k < 3) {
        const float* yy = y + ((size_t)(b * 514 + i + k)) * 6;
        float cx = yy[0], cy = yy[1], a = yy[2];
        float ox = -0.05f * sinf(a), oy = 0.05f * cosf(a);
        float* tmp = ts + OF_HC;                // temp scratch (overwritten later)
        tmp[k * 4 + 0] = cx; tmp[k * 4 + 1] = cy;
        tmp[k * 4 + 2] = ox; tmp[k * 4 + 3] = oy;
        if (k == 1) { ts[OF_OFF] = ox; ts[OF_OFF + 1] = oy; }
    }
    __syncthreads();
    if (k < 3) {
        const float* tmp = ts + OF_HC;
        float vx, vy, a0, a1;
        if (k == 0)      { vx = tmp[0] - tmp[4]; vy = tmp[1] - tmp[5]; a0 = 1.f; a1 = 0.f; } // edge 1->4
        else if (k == 1) { vx = -tmp[6];         vy = -tmp[7];         a0 = 0.f; a1 = 1.f; } // edge 4->3
        else             { vx =  tmp[6];         vy =  tmp[7];         a0 = 0.f; a1 = 1.f; } // edge 4->5
        float r   = sqrtf(vx * vx + vy * vy);
        float inv = 1.0f / (r + 1e-12f);
        float ux = vx * inv, uy = vy * inv;
        ts[OF_U + k * 4 + 0] = ux; ts[OF_U + k * 4 + 1] = uy; ts[OF_U + k * 4 + 2] = 0.f;
        float tt = fminf(r * (1.0f / 0.06f), 1.0f);
        float fc = 0.5f * (cosf(3.14159265358979323846f * tt) + 1.0f);
        ts[OF_FCUT + k] = fc;
        #pragma unroll
        for (int ib = 0; ib < 10; ib++) {
            float z = r * 150.0f - (float)ib;   // (r - ib*width)/width, width = 0.06/9
            ts[OF_EMB + k * 12 + ib] = __expf(-z * z) * fc;
        }
        ts[OF_EMB + k * 12 + 10] = a0;
        ts[OF_EMB + k * 12 + 11] = a1;
        float u3[3] = {ux, uy, 0.f};
        #pragma unroll
        for (int rr = 0; rr < 3; rr++)
            #pragma unroll
            for (int cc2 = 0; cc2 < 3; cc2++)
                ts[OF_Y2 + k * 9 + rr * 3 + cc2] = u3[rr] * u3[cc2] - (rr == cc2 ? (1.0f / 3.0f) : 0.0f);
    }
    // ---------------- state init ----------------
    if (k < CC) {
        float e0 = Wemb[k], e1 = Wemb[50 + k], e2 = Wemb[100 + k];
        ts[OF_S + 0 * CC + k] = e0 + e1;  // node1 (center)
        ts[OF_S + 1 * CC + k] = e0 + e1;  // node4 (center)
        ts[OF_S + 2 * CC + k] = e0 + e2;  // node3
        ts[OF_S + 3 * CC + k] = e0 + e2;  // node5
        #pragma unroll
        for (int vi = 0; vi < 3; vi++)
            #pragma unroll
            for (int d = 0; d < 3; d++)
                ts[OF_V + (vi * CC + k) * 3 + d] = 0.0f;
    }

    // ---------------- layer loop ----------------
    for (int l = 0; l < 6; l++) {
        __syncthreads();
        // --- stage weights ---
        {
            const float* wr2g = Wr2g + l * 16000;
            for (int idx = tid; idx < 16128; idx += NTHR) {
                int j = idx / 252, cc2 = idx - j * 252;
                sm[WR2_OFF + idx] = (cc2 < 250) ? wr2g[j * 250 + cc2] : 0.0f;
            }
            for (int idx = tid; idx < 768; idx += NTHR)
                sm[WR1_OFF + idx] = Wr1g[l * 768 + idx];
            if (tid < 64) sm[BR1_OFF + tid] = br1g[l * 64 + tid];
            for (int idx = tid; idx < 2500; idx += NTHR) {
                sm[WS_OFF + idx] = Wsg[l * 2500 + idx];
                sm[WG_OFF + idx] = Wgg[l * 2500 + idx];
                sm[WV_OFF + idx] = Wvg[l * 2500 + idx];
            }
        }
        __syncthreads();

        // --- phase A: hidden = silu(emb @ Wr1 + br1), per edge ---
        {
            float acc0 = sm[BR1_OFF + k], acc1 = acc0, acc2 = acc0;
            #pragma unroll
            for (int ii = 0; ii < 12; ii++) {
                float wv_ = sm[WR1_OFF + ii * 64 + k];
                acc0 += ts[OF_EMB + 0 * 12 + ii] * wv_;
                acc1 += ts[OF_EMB + 1 * 12 + ii] * wv_;
                acc2 += ts[OF_EMB + 2 * 12 + ii] * wv_;
            }
            ts[OF_HID + k * 4 + 0] = silu_f(acc0);
            ts[OF_HID + k * 4 + 1] = silu_f(acc1);
            ts[OF_HID + k * 4 + 2] = silu_f(acc2);
        }
        __syncthreads();

        // --- phase B: w[e][col] = (hidden[e] @ Wr2)[col] * fcut[e] ---
        if (k < 63) {
            const float4* wr2f = (const float4*)(sm + WR2_OFF);   // row j: [j*63 + k]
            const float4* hidf = (const float4*)(ts + OF_HID);
            float4 a0 = {0,0,0,0}, a1 = {0,0,0,0}, a2 = {0,0,0,0};
            #pragma unroll 8
            for (int j = 0; j < 64; j++) {
                float4 wq = wr2f[j * 63 + k];
                float4 hq = hidf[j];
                a0.x += hq.x * wq.x; a0.y += hq.x * wq.y; a0.z += hq.x * wq.z; a0.w += hq.x * wq.w;
                a1.x += hq.y * wq.x; a1.y += hq.y * wq.y; a1.z += hq.y * wq.z; a1.w += hq.y * wq.w;
                a2.x += hq.z * wq.x; a2.y += hq.z * wq.y; a2.z += hq.z * wq.z; a2.w += hq.z * wq.w;
            }
            float fc0 = ts[OF_FCUT + 0], fc1 = ts[OF_FCUT + 1], fc2 = ts[OF_FCUT + 2];
            float4* wout = (float4*)(ts + OF_W);
            wout[k]       = make_float4(a0.x * fc0, a0.y * fc0, a0.z * fc0, a0.w * fc0);
            wout[63 + k]  = make_float4(a1.x * fc1, a1.y * fc1, a1.z * fc1, a1.w * fc1);
            wout[126 + k] = make_float4(a2.x * fc2, a2.y * fc2, a2.z * fc2, a2.w * fc2);
        }
        __syncthreads();

        // --- phase M: messages + build hC/vC ---
        if (k < CC) {
            const float* w0 = ts + OF_W;
            const float* w1 = ts + OF_W + 252;
            const float* w2 = ts + OF_W + 504;
            float s1 = ts[OF_S + k], s4 = ts[OF_S + CC + k];
            float v4x = ts[OF_V + k * 3], v4y = ts[OF_V + k * 3 + 1], v4z = ts[OF_V + k * 3 + 2];
            float u0x = ts[OF_U + 0], u0y = ts[OF_U + 1];
            float u1x = ts[OF_U + 4], u1y = ts[OF_U + 5];
            float u2x = ts[OF_U + 8], u2y = ts[OF_U + 9];

            // edge 1->4 (src v == 0)
            float ms4  = w0[k] * s1;
            float w01  = w0[50 + k] * s1;
            float mv4x = w01 * u0x, mv4y = w01 * u0y, mv4z = 0.0f;

            // edge 4->3
            float dot1 = v4x * u1x + v4y * u1y;
            float ms3  = w1[k] * s4 + w1[100 + k] * dot1;
            float cr1x = -v4z * u1y, cr1y = v4z * u1x, cr1z = v4x * u1y - v4y * u1x;
            const float* Ya = ts + OF_Y2 + 9;
            float y1x = v4x * Ya[0] + v4y * Ya[3] + v4z * Ya[6];
            float y1y = v4x * Ya[1] + v4y * Ya[4] + v4z * Ya[7];
            float y1z = v4x * Ya[2] + v4y * Ya[5] + v4z * Ya[8];
            float w11 = w1[50 + k] * s4, w13 = w1[150 + k], w14 = w1[200 + k];
            float mv3x = w11 * u1x + w13 * cr1x + w14 * y1x;
            float mv3y = w11 * u1y + w13 * cr1y + w14 * y1y;
            float mv3z =             w13 * cr1z + w14 * y1z;

            // edge 4->5
            float dot2 = v4x * u2x + v4y * u2y;
            float ms5  = w2[k] * s4 + w2[100 + k] * dot2;
            float cr2x = -v4z * u2y, cr2y = v4z * u2x, cr2z = v4x * u2y - v4y * u2x;
            const float* Yb = ts + OF_Y2 + 18;
            float y2x = v4x * Yb[0] + v4y * Yb[3] + v4z * Yb[6];
            float y2y = v4x * Yb[1] + v4y * Yb[4] + v4z * Yb[7];
            float y2z = v4x * Yb[2] + v4y * Yb[5] + v4z * Yb[8];
            float w21 = w2[50 + k] * s4, w23 = w2[150 + k], w24 = w2[200 + k];
            float mv5x = w21 * u2x + w23 * cr2x + w24 * y2x;
            float mv5y = w21 * u2y + w23 * cr2y + w24 * y2y;
            float mv5z =             w23 * cr2z + w24 * y2z;

            ((float4*)(ts + OF_HC))[k] = make_float4(
                s1,
                s4 + ms4,
                ts[OF_S + 2 * CC + k] + ms3,
                ts[OF_S + 3 * CC + k] + ms5);

            float* vc = ts + OF_VC + k * 12;
            vc[0] = v4x + mv4x; vc[1] = v4y + mv4y; vc[2] = v4z + mv4z;
            vc[3] = ts[OF_V + (1 * CC + k) * 3 + 0] + mv3x;
            vc[4] = ts[OF_V + (1 * CC + k) * 3 + 1] + mv3y;
            vc[5] = ts[OF_V + (1 * CC + k) * 3 + 2] + mv3z;
            vc[6] = ts[OF_V + (2 * CC + k) * 3 + 0] + mv5x;
            vc[7] = ts[OF_V + (2 * CC + k) * 3 + 1] + mv5y;
            vc[8] = ts[OF_V + (2 * CC + k) * 3 + 2] + mv5z;
        }
        __syncthreads();

        // --- phase G: node GEMMs (Ws, Wg, Wv) ---
        if (k < CC) {
            float sa0 = 0.f, sa1 = 0.f, sa2 = 0.f, sa3 = 0.f;
            float ga0 = 0.f, ga1 = 0.f, ga2 = 0.f;
            float va0=0.f,va1=0.f,va2=0.f,va3=0.f,va4=0.f,va5=0.f,va6=0.f,va7=0.f,va8=0.f;
            const float4* hc = (const float4*)(ts + OF_HC);
            const float4* vc = (const float4*)(ts + OF_VC);
            #pragma unroll 2
            for (int c = 0; c < CC; c++) {
                float ws = sm[WS_OFF + c * 50 + k];
                float wg = sm[WG_OFF + c * 50 + k];
                float wv = sm[WV_OFF + c * 50 + k];
                float4 h = hc[c];
                sa0 += h.x * ws; sa1 += h.y * ws; sa2 += h.z * ws; sa3 += h.w * ws;
                ga0 += h.y * wg; ga1 += h.z * wg; ga2 += h.w * wg;
                float4 p = vc[c * 3 + 0], q = vc[c * 3 + 1], r2 = vc[c * 3 + 2];
                va0 += p.x * wv; va1 += p.y * wv; va2 += p.z * wv;
                va3 += p.w * wv; va4 += q.x * wv; va5 += q.y * wv;
                va6 += q.z * wv; va7 += q.w * wv; va8 += r2.x * wv;
            }
            ts[OF_S + 0 * CC + k] = silu_f(sa0);
            ts[OF_S + 1 * CC + k] = silu_f(sa1);
            ts[OF_S + 2 * CC + k] = silu_f(sa2);
            ts[OF_S + 3 * CC + k] = silu_f(sa3);
            float g0 = sigm_f(ga0), g1 = sigm_f(ga1), g2 = sigm_f(ga2);
            ts[OF_V + (0 * CC + k) * 3 + 0] = va0 * g0;
            ts[OF_V + (0 * CC + k) * 3 + 1] = va1 * g0;
            ts[OF_V + (0 * CC + k) * 3 + 2] = va2 * g0;
            ts[OF_V + (1 * CC + k) * 3 + 0] = va3 * g1;
            ts[OF_V + (1 * CC + k) * 3 + 1] = va4 * g1;
            ts[OF_V + (1 * CC + k) * 3 + 2] = va5 * g1;
            ts[OF_V + (2 * CC + k) * 3 + 0] = va6 * g2;
            ts[OF_V + (2 * CC + k) * 3 + 1] = va7 * g2;
            ts[OF_V + (2 * CC + k) * 3 + 2] = va8 * g2;
        }
    }
    __syncthreads();

    // ---------------- output ----------------
    if (k < 6) {
        int vi = k >> 1, d = k & 1;      // vi: 0=n4, 1=n3, 2=n5; d: 0=x, 1=y
        float acc = 0.0f;
        #pragma unroll 5
        for (int c = 0; c < CC; c++)
            acc += ts[OF_V + (vi * CC + c) * 3 + d] * __ldg(Woutg + c);
        ts[OF_HC + k] = acc;
    }
    __syncthreads();
    if (k == 0) {
        float o4x = ts[OF_HC + 0], o4y = ts[OF_HC + 1];
        float o3x = ts[OF_HC + 2], o3y = ts[OF_HC + 3];
        float o5x = ts[OF_HC + 4], o5y = ts[OF_HC + 5];
        float ox = ts[OF_OFF], oy = ts[OF_OFF + 1];
        float* dst = outp + ((size_t)(b * 514 + i + 1)) * 3;
        dst[0] = o3x + o4x + o5x;
        dst[1] = o3y + o4y + o5y;
        dst[2] = ox * (o3y - o5y) - oy * (o3x - o5x);
    }
}

extern "C" void kernel_launch(void* const* d_in, const int* in_sizes, int n_in,
                              void* d_out, int out_size) {
    const float* y    = (const float*)d_in[0];
    const float* Wemb = (const float*)d_in[1];
    const float* Wr1  = (const float*)d_in[2];
    const float* br1  = (const float*)d_in[3];
    const float* Wr2  = (const float*)d_in[4];
    const float* Ws   = (const float*)d_in[5];
    const float* Wv   = (const float*)d_in[6];
    const float* Wg   = (const float*)d_in[7];
    const float* Wo   = (const float*)d_in[8];
    float* outp = (float*)d_out;

    // reference output is zeros outside rows [1, L-2]
    cudaMemsetAsync(outp, 0, (size_t)out_size * sizeof(float));

    cudaFuncSetAttribute(e3nn_kernel, cudaFuncAttributeMaxDynamicSharedMemorySize, SMEM_BYTES);
    e3nn_kernel<<<NBLK, NTHR, SMEM_BYTES>>>(y, Wemb, Wr1, br1, Wr2, Ws, Wv, Wg, Wo, outp);
}

// round 2
// speedup vs baseline: 1.3166x; 1.3166x over previous
#include <cuda_runtime.h>
#include <math.h>

// E3nnForce fused kernel, round 2.
//  * Pruned graph: only nodes {1,4,3,5} and edges (1->4),(4->3),(4->5) are live.
//  * Phase B (radial 64->250 GEMM) is CTA-cooperative: Wr2 read once per CTA
//    straight from global; outputs for all 8 triplets in one pass.
//  * f32x2 packed FMA everywhere in the hot GEMM loops.
//  * s/hC state and v/vC state live in single in-place arrays -> smem 107KB,
//    2 CTAs/SM.

#define CC 50
#define TRIPS 8
#define NBLK 4096
#define NTHR 512

typedef unsigned long long ull;

// ---- block-level smem layout (floats) ----
#define WR1S  0            // 12 x 64
#define BR1S  768          // 64
#define WSS   832          // 50 x 50
#define WGS   3332
#define WVS   5832
#define HID2  8336         // [trip][j][8] : {e0,e0,e1,e1,e2,e2,pad,pad}
#define WALL  12432        // [24][252]    : radial weights per (trip,edge)
#define FCUTD 18480        // [8][3][2]    : {fc,fc}
#define TST   18528        // per-trip regions
#define TSF   1104
#define SMEM_FLOATS (TST + TRIPS * TSF)     // 27360
#define SMEM_BYTES  (SMEM_FLOATS * 4)       // 109440

// ---- per-trip layout (floats, relative) ----
#define OF_S4   0     // float4[50]: (s1, s4, s3, s5)  (doubles as hC)
#define OF_HG   200   // float4[50]: (h4, h3, h5, 0)   (gate-GEMM operand)
#define OF_VC   400   // [50][12]: v4x v4y v4z v3x | v3y v3z v5x v5y | v5z 0 0 0
#define OF_U    1008  // u[3][4]
#define OF_EMB  1020  // emb[3][12]
#define OF_Y2   1056  // Y2[3][9]
#define OF_OFF  1084  // off1 x,y
#define OF_OUTS 1088  // epilogue scratch[6]

__device__ __forceinline__ float sigm_f(float x) { return 1.0f / (1.0f + __expf(-x)); }
__device__ __forceinline__ float silu_f(float x) { return x / (1.0f + __expf(-x)); }

__device__ __forceinline__ ull fma2(ull a, ull b, ull c) {
    ull d;
    asm("fma.rn.f32x2 %0, %1, %2, %3;" : "=l"(d) : "l"(a), "l"(b), "l"(c));
    return d;
}
__device__ __forceinline__ ull mul2(ull a, ull b) {
    ull d;
    asm("mul.rn.f32x2 %0, %1, %2;" : "=l"(d) : "l"(a), "l"(b));
    return d;
}
__device__ __forceinline__ ull pack2(float lo, float hi) {
    ull d;
    asm("mov.b64 %0, {%1, %2};" : "=l"(d) : "f"(lo), "f"(hi));
    return d;
}
__device__ __forceinline__ void unpack2(ull v, float& lo, float& hi) {
    asm("mov.b64 {%0, %1}, %2;" : "=f"(lo), "=f"(hi) : "l"(v));
}

__global__ void __launch_bounds__(NTHR, 2)
e3nn_kernel(const float* __restrict__ y,
            const float* __restrict__ Wemb,
            const float* __restrict__ Wr1g,
            const float* __restrict__ br1g,
            const float* __restrict__ Wr2g,
            const float* __restrict__ Wsg,
            const float* __restrict__ Wvg,
            const float* __restrict__ Wgg,
            const float* __restrict__ Woutg,
            float* __restrict__ outp)
{
    extern __shared__ float sm[];
    const int tid  = threadIdx.x;
    const int trip = tid >> 6;
    const int k    = tid & 63;
    float* ts = sm + TST + trip * TSF;

    const int t = blockIdx.x * TRIPS + trip;
    const int b = t >> 9;
    const int i = t & 511;

    // ---------------- geometry ----------------
    float* scratch = sm + WALL + trip * 16;     // WALL is free pre-loop
    if (k < 3) {
        const float* yy = y + ((size_t)(b * 514 + i + k)) * 6;
        float cx = yy[0], cy = yy[1], a = yy[2];
        float ox = -0.05f * sinf(a), oy = 0.05f * cosf(a);
        scratch[k * 4 + 0] = cx; scratch[k * 4 + 1] = cy;
        scratch[k * 4 + 2] = ox; scratch[k * 4 + 3] = oy;
        if (k == 1) { ts[OF_OFF] = ox; ts[OF_OFF + 1] = oy; }
    }
    __syncthreads();
    if (k < 3) {
        float vx, vy, a0, a1;
        if (k == 0)      { vx = scratch[0] - scratch[4]; vy = scratch[1] - scratch[5]; a0 = 1.f; a1 = 0.f; } // 1->4
        else if (k == 1) { vx = -scratch[6];             vy = -scratch[7];             a0 = 0.f; a1 = 1.f; } // 4->3
        else             { vx =  scratch[6];             vy =  scratch[7];             a0 = 0.f; a1 = 1.f; } // 4->5
        float r   = sqrtf(vx * vx + vy * vy);
        float inv = 1.0f / (r + 1e-12f);
        float ux = vx * inv, uy = vy * inv;
        ts[OF_U + k * 4 + 0] = ux; ts[OF_U + k * 4 + 1] = uy; ts[OF_U + k * 4 + 2] = 0.f;
        float tt = fminf(r * (1.0f / 0.06f), 1.0f);
        float fc = 0.5f * (cosf(3.14159265358979323846f * tt) + 1.0f);
        *(ull*)(sm + FCUTD + (trip * 3 + k) * 2) = pack2(fc, fc);
        #pragma unroll
        for (int ib = 0; ib < 10; ib++) {
            float z = r * 150.0f - (float)ib;
            ts[OF_EMB + k * 12 + ib] = __expf(-z * z) * fc;
        }
        ts[OF_EMB + k * 12 + 10] = a0;
        ts[OF_EMB + k * 12 + 11] = a1;
        float u3[3] = {ux, uy, 0.f};
        #pragma unroll
        for (int rr = 0; rr < 3; rr++)
            #pragma unroll
            for (int cc2 = 0; cc2 < 3; cc2++)
                ts[OF_Y2 + k * 9 + rr * 3 + cc2] = u3[rr] * u3[cc2] - (rr == cc2 ? (1.0f / 3.0f) : 0.0f);
    }
    if (k < CC) {
        float e0 = Wemb[k], e1 = Wemb[50 + k], e2 = Wemb[100 + k];
        *(float4*)(ts + OF_S4 + k * 4) = make_float4(e0 + e1, e0 + e1, e0 + e2, e0 + e2);
        float4 z4 = make_float4(0.f, 0.f, 0.f, 0.f);
        *(float4*)(ts + OF_VC + k * 12 + 0) = z4;
        *(float4*)(ts + OF_VC + k * 12 + 4) = z4;
        *(float4*)(ts + OF_VC + k * 12 + 8) = z4;
    }

    // ---------------- layers ----------------
    for (int l = 0; l < 6; l++) {
        __syncthreads();
        // ---- stage node weights + radial-MLP-1 ----
        {
            const float4* wsg4 = (const float4*)(Wsg + (size_t)l * 2500);
            const float4* wgg4 = (const float4*)(Wgg + (size_t)l * 2500);
            const float4* wvg4 = (const float4*)(Wvg + (size_t)l * 2500);
            float4* wss4 = (float4*)(sm + WSS);
            float4* wgs4 = (float4*)(sm + WGS);
            float4* wvs4 = (float4*)(sm + WVS);
            for (int idx = tid; idx < 625; idx += NTHR) {
                wss4[idx] = wsg4[idx];
                wgs4[idx] = wgg4[idx];
                wvs4[idx] = wvg4[idx];
            }
            if (tid < 192) ((float4*)(sm + WR1S))[tid] = ((const float4*)(Wr1g + (size_t)l * 768))[tid];
            else if (tid < 208) ((float4*)(sm + BR1S))[tid - 192] = ((const float4*)(br1g + (size_t)l * 64))[tid - 192];
        }
        __syncthreads();

        // ---- phase A: hidden = silu(emb @ Wr1 + br1), duplicated pairs ----
        {
            float acc0 = sm[BR1S + k], acc1 = acc0, acc2 = acc0;
            const float* emb = ts + OF_EMB;
            #pragma unroll
            for (int ii = 0; ii < 12; ii++) {
                float wv_ = sm[WR1S + ii * 64 + k];
                acc0 += emb[ii]      * wv_;
                acc1 += emb[12 + ii] * wv_;
                acc2 += emb[24 + ii] * wv_;
            }
            float* hp = sm + HID2 + (trip * 64 + k) * 8;
            float h0 = silu_f(acc0), h1 = silu_f(acc1), h2 = silu_f(acc2);
            *(ull*)(hp + 0) = pack2(h0, h0);
            *(ull*)(hp + 2) = pack2(h1, h1);
            *(ull*)(hp + 4) = pack2(h2, h2);
        }
        __syncthreads();

        // ---- phase B: w = (hidden @ Wr2) * fcut, CTA-cooperative ----
        {
            const int p = tid >> 7;       // trip pair 0..3
            const int q = tid & 127;      // column pair 0..124
            if (q < 125) {
                const int col0 = q * 2;
                const bool full = (col0 < 100);   // edge-0 cols beyond 100 are dead
                const float* wbase = Wr2g + (size_t)l * 16000 + col0;
                const int t0 = p * 2, t1 = p * 2 + 1;
                const float* h0b = sm + HID2 + t0 * 512;
                const float* h1b = sm + HID2 + t1 * 512;
                ull a0 = 0, a1 = 0, a2 = 0, a3 = 0, a4 = 0, a5 = 0;
                #pragma unroll 4
                for (int j = 0; j < 64; j++) {
                    ull wv = __ldg((const ull*)(wbase + j * 250));
                    ulonglong2 hA = *(const ulonglong2*)(h0b + j * 8);
                    ull hA2      = *(const ull*)(h0b + j * 8 + 4);
                    ulonglong2 hB = *(const ulonglong2*)(h1b + j * 8);
                    ull hB2      = *(const ull*)(h1b + j * 8 + 4);
                    a1 = fma2(hA.y, wv, a1);
                    a2 = fma2(hA2,  wv, a2);
                    a4 = fma2(hB.y, wv, a4);
                    a5 = fma2(hB2,  wv, a5);
                    if (full) {
                        a0 = fma2(hA.x, wv, a0);
                        a3 = fma2(hB.x, wv, a3);
                    }
                }
                const ull* fcd = (const ull*)(sm + FCUTD);
                float* wall = sm + WALL;
                if (full) {
                    *(ull*)(wall + (t0 * 3 + 0) * 252 + col0) = mul2(a0, fcd[t0 * 3 + 0]);
                    *(ull*)(wall + (t1 * 3 + 0) * 252 + col0) = mul2(a3, fcd[t1 * 3 + 0]);
                }
                *(ull*)(wall + (t0 * 3 + 1) * 252 + col0) = mul2(a1, fcd[t0 * 3 + 1]);
                *(ull*)(wall + (t0 * 3 + 2) * 252 + col0) = mul2(a2, fcd[t0 * 3 + 2]);
                *(ull*)(wall + (t1 * 3 + 1) * 252 + col0) = mul2(a4, fcd[t1 * 3 + 1]);
                *(ull*)(wall + (t1 * 3 + 2) * 252 + col0) = mul2(a5, fcd[t1 * 3 + 2]);
            }
        }
        __syncthreads();

        // ---- phase M: messages, in-place state update ----
        if (k < CC) {
            const float* w0 = sm + WALL + (trip * 3 + 0) * 252;
            const float* w1 = sm + WALL + (trip * 3 + 1) * 252;
            const float* w2 = sm + WALL + (trip * 3 + 2) * 252;
            float4 s = *(const float4*)(ts + OF_S4 + k * 4);
            float* vcp = ts + OF_VC + k * 12;
            float v4x = vcp[0], v4y = vcp[1], v4z = vcp[2];
            float v3x = vcp[3], v3y = vcp[4], v3z = vcp[5];
            float v5x = vcp[6], v5y = vcp[7], v5z = vcp[8];
            float u0x = ts[OF_U + 0], u0y = ts[OF_U + 1];
            float u1x = ts[OF_U + 4], u1y = ts[OF_U + 5];
            float u2x = ts[OF_U + 8], u2y = ts[OF_U + 9];
            float s1 = s.x, s4v = s.y;

            // edge 1->4 (src v == 0 -> paths 0,1 only)
            float ms4  = w0[k] * s1;
            float w01  = w0[50 + k] * s1;
            float mv4x = w01 * u0x, mv4y = w01 * u0y;

            // edge 4->3
            float dot1 = v4x * u1x + v4y * u1y;
            float ms3  = w1[k] * s4v + w1[100 + k] * dot1;
            float cr1x = -v4z * u1y, cr1y = v4z * u1x, cr1z = v4x * u1y - v4y * u1x;
            const float* Ya = ts + OF_Y2 + 9;
            float y1x = v4x * Ya[0] + v4y * Ya[3] + v4z * Ya[6];
            float y1y = v4x * Ya[1] + v4y * Ya[4] + v4z * Ya[7];
            float y1z = v4x * Ya[2] + v4y * Ya[5] + v4z * Ya[8];
            float w11 = w1[50 + k] * s4v, w13 = w1[150 + k], w14 = w1[200 + k];
            float mv3x = w11 * u1x + w13 * cr1x + w14 * y1x;
            float mv3y = w11 * u1y + w13 * cr1y + w14 * y1y;
            float mv3z =             w13 * cr1z + w14 * y1z;

            // edge 4->5
            float dot2 = v4x * u2x + v4y * u2y;
            float ms5  = w2[k] * s4v + w2[100 + k] * dot2;
            float cr2x = -v4z * u2y, cr2y = v4z * u2x, cr2z = v4x * u2y - v4y * u2x;
            const float* Yb = ts + OF_Y2 + 18;
            float y2x = v4x * Yb[0] + v4y * Yb[3] + v4z * Yb[6];
            float y2y = v4x * Yb[1] + v4y * Yb[4] + v4z * Yb[7];
            float y2z = v4x * Yb[2] + v4y * Yb[5] + v4z * Yb[8];
            float w21 = w2[50 + k] * s4v, w23 = w2[150 + k], w24 = w2[200 + k];
            float mv5x = w21 * u2x + w23 * cr2x + w24 * y2x;
            float mv5y = w21 * u2y + w23 * cr2y + w24 * y2y;
            float mv5z =             w23 * cr2z + w24 * y2z;

            float h4 = s4v + ms4, h3 = s.z + ms3, h5 = s.w + ms5;
            *(float4*)(ts + OF_S4 + k * 4) = make_float4(s1, h4, h3, h5);
            *(float4*)(ts + OF_HG + k * 4) = make_float4(h4, h3, h5, 0.0f);
            *(float4*)(vcp + 0) = make_float4(v4x + mv4x, v4y + mv4y, v4z, v3x + mv3x);
            *(float4*)(vcp + 4) = make_float4(v3y + mv3y, v3z + mv3z, v5x + mv5x, v5y + mv5y);
            *(float4*)(vcp + 8) = make_float4(v5z + mv5z, 0.f, 0.f, 0.f);
        }
        __syncthreads();

        // ---- phase G: node GEMMs, f32x2 packed ----
        ull sacc0 = 0, sacc1 = 0, gacc0 = 0, gacc1 = 0;
        ull vA = 0, vB = 0, vCz = 0, vD = 0, vE = 0;
        if (k < CC) {
            const float* wssp = sm + WSS + k;
            const float* wgsp = sm + WGS + k;
            const float* wvsp = sm + WVS + k;
            const float* s4b = ts + OF_S4;
            const float* hgb = ts + OF_HG;
            const float* vcb = ts + OF_VC;
            #pragma unroll 2
            for (int c = 0; c < CC; c++) {
                float ws = wssp[c * 50], wg = wgsp[c * 50], wv = wvsp[c * 50];
                ull wsd = pack2(ws, ws), wgd = pack2(wg, wg), wvd = pack2(wv, wv);
                ulonglong2 sp = *(const ulonglong2*)(s4b + c * 4);
                ulonglong2 hp = *(const ulonglong2*)(hgb + c * 4);
                ulonglong2 va = *(const ulonglong2*)(vcb + c * 12);
                ulonglong2 vb = *(const ulonglong2*)(vcb + c * 12 + 4);
                ull vc2       = *(const ull*)(vcb + c * 12 + 8);
                sacc0 = fma2(sp.x, wsd, sacc0);
                sacc1 = fma2(sp.y, wsd, sacc1);
                gacc0 = fma2(hp.x, wgd, gacc0);
                gacc1 = fma2(hp.y, wgd, gacc1);
                vA = fma2(va.x, wvd, vA);
                vB = fma2(va.y, wvd, vB);
                vCz = fma2(vb.x, wvd, vCz);
                vD = fma2(vb.y, wvd, vD);
                vE = fma2(vc2, wvd, vE);
            }
        }
        __syncthreads();
        if (k < CC) {
            float s1p, s4p, s3p, s5p;
            unpack2(sacc0, s1p, s4p);
            unpack2(sacc1, s3p, s5p);
            *(float4*)(ts + OF_S4 + k * 4) =
                make_float4(silu_f(s1p), silu_f(s4p), silu_f(s3p), silu_f(s5p));
            float g4p, g3p, g5p, gxx;
            unpack2(gacc0, g4p, g3p);
            unpack2(gacc1, g5p, gxx);
            float g4 = sigm_f(g4p), g3 = sigm_f(g3p), g5 = sigm_f(g5p);
            float V4x, V4y, V4z, V3x, V3y, V3z, V5x, V5y, V5z, vxx;
            unpack2(vA, V4x, V4y);
            unpack2(vB, V4z, V3x);
            unpack2(vCz, V3y, V3z);
            unpack2(vD, V5x, V5y);
            unpack2(vE, V5z, vxx);
            float* vcp = ts + OF_VC + k * 12;
            *(float4*)(vcp + 0) = make_float4(V4x * g4, V4y * g4, V4z * g4, V3x * g3);
            *(float4*)(vcp + 4) = make_float4(V3y * g3, V3z * g3, V5x * g5, V5y * g5);
            *(float4*)(vcp + 8) = make_float4(V5z * g5, 0.f, 0.f, 0.f);
        }
    }
    __syncthreads();

    // ---------------- output ----------------
    if (k < 6) {
        int off = (k >> 1) * 3 + (k & 1);   // n4:{0,1} n3:{3,4} n5:{6,7}
        float acc = 0.0f;
        const float* vcb = ts + OF_VC;
        #pragma unroll 5
        for (int c = 0; c < CC; c++)
            acc += vcb[c * 12 + off] * __ldg(Woutg + c);
        ts[OF_OUTS + k] = acc;
    }
    __syncthreads();
    if (k == 0) {
        float o4x = ts[OF_OUTS + 0], o4y = ts[OF_OUTS + 1];
        float o3x = ts[OF_OUTS + 2], o3y = ts[OF_OUTS + 3];
        float o5x = ts[OF_OUTS + 4], o5y = ts[OF_OUTS + 5];
        float ox = ts[OF_OFF], oy = ts[OF_OFF + 1];
        float* dst = outp + ((size_t)(b * 514 + i + 1)) * 3;
        dst[0] = o3x + o4x + o5x;
        dst[1] = o3y + o4y + o5y;
        dst[2] = ox * (o3y - o5y) - oy * (o3x - o5x);
    }
}

extern "C" void kernel_launch(void* const* d_in, const int* in_sizes, int n_in,
                              void* d_out, int out_size) {
    const float* y    = (const float*)d_in[0];
    const float* Wemb = (const float*)d_in[1];
    const float* Wr1  = (const float*)d_in[2];
    const float* br1  = (const float*)d_in[3];
    const float* Wr2  = (const float*)d_in[4];
    const float* Ws   = (const float*)d_in[5];
    const float* Wv   = (const float*)d_in[6];
    const float* Wg   = (const float*)d_in[7];
    const float* Wo   = (const float*)d_in[8];
    float* outp = (float*)d_out;

    cudaMemsetAsync(outp, 0, (size_t)out_size * sizeof(float));

    cudaFuncSetAttribute(e3nn_kernel, cudaFuncAttributeMaxDynamicSharedMemorySize, SMEM_BYTES);
    e3nn_kernel<<<NBLK, NTHR, SMEM_BYTES>>>(y, Wemb, Wr1, br1, Wr2, Ws, Wv, Wg, Wo, outp);
}